// round 2
// baseline (speedup 1.0000x reference)
#include <cuda_runtime.h>
#include <cstdint>

// ============================================================================
// out[524288,128] = x @ P^T, P = Sinkhorn(exp(clip((logits+gumbel(u))/3)))
// Inputs: x f32 [524288,128], logits f32 [128,128], u f32 [128,128]
// NOTE: harness PTX targets compute_103 (no 'a') -> tcgen05 unavailable.
// Use classic mma.sync tf32 (sm_80+ baseline feature).
// ============================================================================

#define EPSF 1e-20f

// P (tf32-rounded, truncation-bias-compensated), written by sinkhorn kernel.
__device__ __align__(16) float d_P[128 * 128];

// ---------------------------------------------------------------------------
// helpers
// ---------------------------------------------------------------------------
__device__ __forceinline__ uint32_t smem_u32(const void* p) {
    uint32_t a;
    asm("{ .reg .u64 t; cvta.to.shared.u64 t, %1; cvt.u32.u64 %0, t; }" : "=r"(a) : "l"(p));
    return a;
}

__device__ __forceinline__ void cp16(float* dst, const float* src) {
    uint32_t d = smem_u32(dst);
    asm volatile("cp.async.cg.shared.global [%0], [%1], 16;" :: "r"(d), "l"(src) : "memory");
}
__device__ __forceinline__ void cp_commit() {
    asm volatile("cp.async.commit_group;" ::: "memory");
}
__device__ __forceinline__ void cp_wait1() {
    asm volatile("cp.async.wait_group 1;" ::: "memory");
}

// ---------------------------------------------------------------------------
// Kernel 1: Sinkhorn. Single block, 512 threads.
// Scaling-vector form: r = 1/(A c), c = 1/(A^T r), 20 iters; P = diag(r) A diag(c).
// ---------------------------------------------------------------------------
__global__ void __launch_bounds__(512, 1)
sinkhorn_kernel(const float* __restrict__ logits, const float* __restrict__ u) {
    extern __shared__ float sh[];
    float* A = sh;                 // 16384
    float* r = sh + 16384;         // 128
    float* c = sh + 16384 + 128;   // 128
    const int tid = threadIdx.x;

    for (int idx = tid; idx < 16384; idx += 512) {
        float uv = u[idx];
        float g  = -logf(-logf(uv + EPSF) + EPSF);
        float la = (logits[idx] + g) * (1.0f / 3.0f);
        la = fminf(10.0f, fmaxf(-10.0f, la));
        A[idx] = expf(la);
    }
    if (tid < 128) c[tid] = 1.0f;
    __syncthreads();

    const int i = tid >> 2;   // row/col index 0..127
    const int s = tid & 3;    // 4-thread segment

    float4 a4[8];
    float  at[32];
#pragma unroll
    for (int k = 0; k < 8; k++)
        a4[k] = *reinterpret_cast<const float4*>(&A[i * 128 + k * 16 + s * 4]);
#pragma unroll
    for (int k = 0; k < 8; k++)
#pragma unroll
        for (int e = 0; e < 4; e++)
            at[k * 4 + e] = A[(k * 16 + s * 4 + e) * 128 + i];

    for (int it = 0; it < 20; it++) {
        float sum = 0.0f;
#pragma unroll
        for (int k = 0; k < 8; k++) {
            float4 cv = *reinterpret_cast<const float4*>(&c[k * 16 + s * 4]);
            sum += a4[k].x * cv.x + a4[k].y * cv.y + a4[k].z * cv.z + a4[k].w * cv.w;
        }
        sum += __shfl_xor_sync(0xffffffffu, sum, 1);
        sum += __shfl_xor_sync(0xffffffffu, sum, 2);
        if (s == 0) r[i] = 1.0f / sum;
        __syncthreads();

        float sum2 = 0.0f;
#pragma unroll
        for (int k = 0; k < 8; k++) {
            float4 rv = *reinterpret_cast<const float4*>(&r[k * 16 + s * 4]);
            sum2 += at[k * 4 + 0] * rv.x + at[k * 4 + 1] * rv.y +
                    at[k * 4 + 2] * rv.z + at[k * 4 + 3] * rv.w;
        }
        sum2 += __shfl_xor_sync(0xffffffffu, sum2, 1);
        sum2 += __shfl_xor_sync(0xffffffffu, sum2, 2);
        if (s == 0) c[i] = 1.0f / sum2;
        __syncthreads();
    }

    // P = diag(r) A diag(c) * (1 + 2^-11)   [compensates mma's RZ truncation of x]
    // then round-to-nearest tf32 so the MMA sees P exactly.
    const float comp = 1.0f + 0.00048828125f;
    for (int idx = tid; idx < 16384; idx += 512) {
        int ri = idx >> 7, cj = idx & 127;
        float p = r[ri] * A[idx] * c[cj] * comp;
        float pt;
        asm("cvt.rna.tf32.f32 %0, %1;" : "=f"(pt) : "f"(p));
        d_P[idx] = pt;
    }
}

// ---------------------------------------------------------------------------
// Kernel 2: persistent tf32 mma.sync GEMM.
// CTA: 256 threads = 8 warps (4 along M x 2 along N). CTA tile 128x128, K=128.
// Warp tile: m32 x n64. P fragments pre-permuted in smem (LDS.64, conflict-free).
// x tile double-buffered via cp.async.cg. Direct STG.64 epilogue (full sectors).
// ---------------------------------------------------------------------------

static constexpr int XS_STRIDE = 132;          // words; conflict-free A-frag LDS
static constexpr int XS_WORDS  = 128 * XS_STRIDE;
static constexpr int PF_FLOATS = 16 * 16 * 32 * 2;   // 16384
static constexpr int GEMM_SMEM = (PF_FLOATS + 2 * XS_WORDS) * 4;  // 200704 B

__global__ void __launch_bounds__(256, 1)
gemm_tf32_kernel(const float* __restrict__ x, float* __restrict__ out, int ntiles) {
    extern __shared__ float sh[];
    float*  PF  = sh;                       // P fragments, float2[8192]
    float*  XS0 = sh + PF_FLOATS;
    float*  XS1 = XS0 + XS_WORDS;

    const int tid  = threadIdx.x;
    const int lane = tid & 31;
    const int wid  = tid >> 5;
    const int wm   = wid & 3;    // 0..3 -> m offset wm*32
    const int wn   = wid >> 2;   // 0..1 -> n offset wn*64

    // ---- prefetch first tile ----
    int t = blockIdx.x;
    const int grid = gridDim.x;
    {
        const float4* g = reinterpret_cast<const float4*>(x) + (size_t)t * 4096;
#pragma unroll
        for (int i = 0; i < 16; i++) {
            int f4 = i * 256 + tid;
            int m = f4 >> 5, c4 = f4 & 31;
            cp16(XS0 + m * XS_STRIDE + c4 * 4, reinterpret_cast<const float*>(g + f4));
        }
    }
    cp_commit();

    // ---- stage P into B-fragment order: float2 pf[(s*16+t)*32+lane] = {B0,B1}
    //      B0 = P[n][k0], B1 = P[n][k0+4], n = 8*nt + lane>>2, k0 = 8*s + lane%4
    float2* PF2 = reinterpret_cast<float2*>(PF);
    for (int p = tid; p < 8192; p += 256) {
        int l = p & 31, nt = (p >> 5) & 15, s = p >> 9;
        int n = nt * 8 + (l >> 2);
        int k0 = s * 8 + (l & 3);
        PF2[p] = make_float2(d_P[n * 128 + k0], d_P[n * 128 + k0 + 4]);
    }
    __syncthreads();

    float* buf[2] = {XS0, XS1};
    int cur = 0;

    for (; t < ntiles; t += grid) {
        // prefetch next tile into the other buffer
        int tn = t + grid;
        if (tn < ntiles) {
            const float4* g = reinterpret_cast<const float4*>(x) + (size_t)tn * 4096;
            float* xb = buf[cur ^ 1];
#pragma unroll
            for (int i = 0; i < 16; i++) {
                int f4 = i * 256 + tid;
                int m = f4 >> 5, c4 = f4 & 31;
                cp16(xb + m * XS_STRIDE + c4 * 4, reinterpret_cast<const float*>(g + f4));
            }
        }
        cp_commit();
        cp_wait1();            // current tile's group complete
        __syncthreads();

        const float* X = buf[cur];

        float acc[2][8][4];
#pragma unroll
        for (int mf = 0; mf < 2; mf++)
#pragma unroll
            for (int nt = 0; nt < 8; nt++)
#pragma unroll
                for (int q = 0; q < 4; q++) acc[mf][nt][q] = 0.0f;

#pragma unroll
        for (int s = 0; s < 16; s++) {
            float2 b[8];
#pragma unroll
            for (int nt = 0; nt < 8; nt++)
                b[nt] = PF2[(s * 16 + wn * 8 + nt) * 32 + lane];

#pragma unroll
            for (int mf = 0; mf < 2; mf++) {
                int r0 = wm * 32 + mf * 16 + (lane >> 2);
                int cc = s * 8 + (lane & 3);
                uint32_t a0 = __float_as_uint(X[r0 * XS_STRIDE + cc]);
                uint32_t a1 = __float_as_uint(X[(r0 + 8) * XS_STRIDE + cc]);
                uint32_t a2 = __float_as_uint(X[r0 * XS_STRIDE + cc + 4]);
                uint32_t a3 = __float_as_uint(X[(r0 + 8) * XS_STRIDE + cc + 4]);
#pragma unroll
                for (int nt = 0; nt < 8; nt++) {
                    asm volatile(
                        "mma.sync.aligned.m16n8k8.row.col.f32.tf32.tf32.f32 "
                        "{%0,%1,%2,%3}, {%4,%5,%6,%7}, {%8,%9}, {%0,%1,%2,%3};"
                        : "+f"(acc[mf][nt][0]), "+f"(acc[mf][nt][1]),
                          "+f"(acc[mf][nt][2]), "+f"(acc[mf][nt][3])
                        : "r"(a0), "r"(a1), "r"(a2), "r"(a3),
                          "r"(__float_as_uint(b[nt].x)), "r"(__float_as_uint(b[nt].y)));
                }
            }
        }

        // ---- epilogue: direct STG.64, each warp-op covers 16 rows x 32B (full sectors)
        float2* og = reinterpret_cast<float2*>(out) + (size_t)t * 128 * 64;
#pragma unroll
        for (int mf = 0; mf < 2; mf++) {
            int r0 = wm * 32 + mf * 16 + (lane >> 2);
#pragma unroll
            for (int nt = 0; nt < 8; nt++) {
                int colp = (wn * 64 + nt * 8 + 2 * (lane & 3)) >> 1;
                og[(size_t)r0 * 64 + colp]       = make_float2(acc[mf][nt][0], acc[mf][nt][1]);
                og[(size_t)(r0 + 8) * 64 + colp] = make_float2(acc[mf][nt][2], acc[mf][nt][3]);
            }
        }
        __syncthreads();   // all warps done with buf[cur] before it is refilled
        cur ^= 1;
    }
}

// ---------------------------------------------------------------------------
// launch
// ---------------------------------------------------------------------------
extern "C" void kernel_launch(void* const* d_in, const int* in_sizes, int n_in,
                              void* d_out, int out_size) {
    const float* x      = (const float*)d_in[0];
    const float* logits = (const float*)d_in[1];
    const float* u      = (const float*)d_in[2];
    float*       out    = (float*)d_out;

    int dev = 0, sms = 148;
    cudaGetDevice(&dev);
    cudaDeviceGetAttribute(&sms, cudaDevAttrMultiProcessorCount, dev);

    const int sink_smem = (16384 + 256) * sizeof(float);  // 66560
    cudaFuncSetAttribute(sinkhorn_kernel, cudaFuncAttributeMaxDynamicSharedMemorySize, sink_smem);
    cudaFuncSetAttribute(gemm_tf32_kernel, cudaFuncAttributeMaxDynamicSharedMemorySize, GEMM_SMEM);

    sinkhorn_kernel<<<1, 512, sink_smem>>>(logits, u);

    int rows   = in_sizes[0] / 128;   // 524288
    int ntiles = rows / 128;          // 4096
    gemm_tf32_kernel<<<sms, 256, GEMM_SMEM>>>(x, out, ntiles);
}

// round 3
// speedup vs baseline: 1.0177x; 1.0177x over previous
#include <cuda_runtime.h>
#include <cstdint>

// ============================================================================
// out[524288,128] = x @ P^T, P = Sinkhorn(exp(clip((logits+gumbel(u))/3)))
// Inputs: x f32 [524288,128], logits f32 [128,128], u f32 [128,128]
// Single fused persistent kernel: per-CTA redundant sinkhorn prologue (P kept
// in smem, fragment-ordered), then tf32 mma.sync GEMM, double-buffered cp.async.
// (tcgen05 unavailable: harness compiles for compute_103, not 103a.)
// ============================================================================

#define EPSF 1e-20f

__device__ __forceinline__ uint32_t smem_u32(const void* p) {
    uint32_t a;
    asm("{ .reg .u64 t; cvta.to.shared.u64 t, %1; cvt.u32.u64 %0, t; }" : "=r"(a) : "l"(p));
    return a;
}
__device__ __forceinline__ void cp16(float* dst, const float* src) {
    uint32_t d = smem_u32(dst);
    asm volatile("cp.async.cg.shared.global [%0], [%1], 16;" :: "r"(d), "l"(src) : "memory");
}
__device__ __forceinline__ void cp_commit() { asm volatile("cp.async.commit_group;" ::: "memory"); }
__device__ __forceinline__ void cp_wait1()  { asm volatile("cp.async.wait_group 1;" ::: "memory"); }

// ---------------------------------------------------------------------------
// smem plan (201,728 B total):
//   PF  : 16384 floats  (P in B-fragment order, float2[8192])
//   XS0 : 128*132 floats (x tile buf 0)
//   XS1 : 128*132 floats (x tile buf 1; holds sinkhorn A during prologue)
//   RC  : 256 floats     (sinkhorn r, c vectors)
// ---------------------------------------------------------------------------
static constexpr int XS_STRIDE = 132;
static constexpr int XS_WORDS  = 128 * XS_STRIDE;
static constexpr int PF_FLOATS = 16384;
static constexpr int SMEM_BYTES = (PF_FLOATS + 2 * XS_WORDS + 256) * 4;

__global__ void __launch_bounds__(512, 1)
fused_kernel(const float* __restrict__ x,
             const float* __restrict__ logits,
             const float* __restrict__ u,
             float* __restrict__ out, int ntiles) {
    extern __shared__ float sh[];
    float*  PF  = sh;
    float*  XS0 = sh + PF_FLOATS;
    float*  XS1 = XS0 + XS_WORDS;
    float*  Rv  = XS1 + XS_WORDS;      // 128
    float*  Cv  = Rv + 128;            // 128
    float2* PF2 = reinterpret_cast<float2*>(PF);

    const int tid  = threadIdx.x;
    const int lane = tid & 31;
    const int wid  = tid >> 5;
    const int wm   = wid & 3;          // 0..3 -> m offset wm*32
    const int wn   = wid >> 2;         // 0..3 -> n offset wn*32

    const int grid = gridDim.x;
    int t = blockIdx.x;

    // ================= prefetch first x tile (hidden under sinkhorn) ========
    {
        const float4* g = reinterpret_cast<const float4*>(x) + (size_t)t * 4096;
#pragma unroll
        for (int i = 0; i < 8; i++) {
            int f4 = i * 512 + tid;
            int m = f4 >> 5, c4 = f4 & 31;
            cp16(XS0 + m * XS_STRIDE + c4 * 4, reinterpret_cast<const float*>(g + f4));
        }
    }
    cp_commit();   // group 0

    // ================= sinkhorn prologue (A lives in XS1) ====================
    {
        float* A = XS1;
        for (int idx = tid; idx < 16384; idx += 512) {
            float uv = u[idx];
            float g  = -logf(-logf(uv + EPSF) + EPSF);
            float la = (logits[idx] + g) * (1.0f / 3.0f);
            la = fminf(10.0f, fmaxf(-10.0f, la));
            A[idx] = expf(la);
        }
        if (tid < 128) Cv[tid] = 1.0f;
        __syncthreads();

        const int i = tid >> 2;   // row/col index
        const int s = tid & 3;

        float4 a4[8];
        float  at[32];
#pragma unroll
        for (int k = 0; k < 8; k++)
            a4[k] = *reinterpret_cast<const float4*>(&A[i * 128 + k * 16 + s * 4]);
#pragma unroll
        for (int k = 0; k < 8; k++)
#pragma unroll
            for (int e = 0; e < 4; e++)
                at[k * 4 + e] = A[(k * 16 + s * 4 + e) * 128 + i];

        for (int it = 0; it < 20; it++) {
            float sum = 0.0f;
#pragma unroll
            for (int k = 0; k < 8; k++) {
                float4 cv = *reinterpret_cast<const float4*>(&Cv[k * 16 + s * 4]);
                sum += a4[k].x * cv.x + a4[k].y * cv.y + a4[k].z * cv.z + a4[k].w * cv.w;
            }
            sum += __shfl_xor_sync(0xffffffffu, sum, 1);
            sum += __shfl_xor_sync(0xffffffffu, sum, 2);
            if (s == 0) Rv[i] = 1.0f / sum;
            __syncthreads();

            float sum2 = 0.0f;
#pragma unroll
            for (int k = 0; k < 8; k++) {
                float4 rv = *reinterpret_cast<const float4*>(&Rv[k * 16 + s * 4]);
                sum2 += at[k * 4 + 0] * rv.x + at[k * 4 + 1] * rv.y +
                        at[k * 4 + 2] * rv.z + at[k * 4 + 3] * rv.w;
            }
            sum2 += __shfl_xor_sync(0xffffffffu, sum2, 1);
            sum2 += __shfl_xor_sync(0xffffffffu, sum2, 2);
            if (s == 0) Cv[i] = 1.0f / sum2;
            __syncthreads();
        }

        // P = diag(r) A diag(c) * (1+2^-11)  [compensates mma RZ-truncation of x],
        // rounded rna->tf32, scattered straight into B-fragment order:
        //   PF2[(s*16 + nt)*32 + lane] = { P[n][k0], P[n][k0+4] }
        //   n = nt*8 + (lane>>2), k0 = s*8 + (lane&3)
        const float comp = 1.0f + 0.00048828125f;
        for (int idx = tid; idx < 16384; idx += 512) {
            int n = idx >> 7, k = idx & 127;
            float p = Rv[n] * A[n * 128 + k] * Cv[k] * comp;
            // note: reference P[n][k] normalized over rows of A then cols; our A
            // is indexed [row][col] with row=n? A is [128,128] logits-shaped; P[n][k]
            // uses A[n][k] with r over rows, c over cols -- consistent with ref.
            float pt;
            asm("cvt.rna.tf32.f32 %0, %1;" : "=f"(pt) : "f"(p));
            int s  = k >> 3, ko = k & 7;
            int fi = ((s * 16 + (n >> 3)) * 32 + (n & 7) * 4 + (ko & 3)) * 2 + (ko >> 2);
            PF[fi] = pt;
        }
        __syncthreads();   // A (XS1) dead; PF ready
    }

    // ================= persistent GEMM mainloop ==============================
    float* buf[2] = {XS0, XS1};
    int cur = 0;

    for (; t < ntiles; t += grid) {
        int tn = t + grid;
        if (tn < ntiles) {
            const float4* g = reinterpret_cast<const float4*>(x) + (size_t)tn * 4096;
            float* xb = buf[cur ^ 1];
#pragma unroll
            for (int i = 0; i < 8; i++) {
                int f4 = i * 512 + tid;
                int m = f4 >> 5, c4 = f4 & 31;
                cp16(xb + m * XS_STRIDE + c4 * 4, reinterpret_cast<const float*>(g + f4));
            }
        }
        cp_commit();
        cp_wait1();          // current tile complete
        __syncthreads();

        const float* X = buf[cur];

        float acc[2][4][4];
#pragma unroll
        for (int mf = 0; mf < 2; mf++)
#pragma unroll
            for (int nt = 0; nt < 4; nt++)
#pragma unroll
                for (int q = 0; q < 4; q++) acc[mf][nt][q] = 0.0f;

#pragma unroll
        for (int s = 0; s < 16; s++) {
            float2 b[4];
#pragma unroll
            for (int nt = 0; nt < 4; nt++)
                b[nt] = PF2[(s * 16 + wn * 4 + nt) * 32 + lane];

#pragma unroll
            for (int mf = 0; mf < 2; mf++) {
                int r0 = wm * 32 + mf * 16 + (lane >> 2);
                int cc = s * 8 + (lane & 3);
                uint32_t a0 = __float_as_uint(X[r0 * XS_STRIDE + cc]);
                uint32_t a1 = __float_as_uint(X[(r0 + 8) * XS_STRIDE + cc]);
                uint32_t a2 = __float_as_uint(X[r0 * XS_STRIDE + cc + 4]);
                uint32_t a3 = __float_as_uint(X[(r0 + 8) * XS_STRIDE + cc + 4]);
#pragma unroll
                for (int nt = 0; nt < 4; nt++) {
                    asm volatile(
                        "mma.sync.aligned.m16n8k8.row.col.f32.tf32.tf32.f32 "
                        "{%0,%1,%2,%3}, {%4,%5,%6,%7}, {%8,%9}, {%0,%1,%2,%3};"
                        : "+f"(acc[mf][nt][0]), "+f"(acc[mf][nt][1]),
                          "+f"(acc[mf][nt][2]), "+f"(acc[mf][nt][3])
                        : "r"(a0), "r"(a1), "r"(a2), "r"(a3),
                          "r"(__float_as_uint(b[nt].x)), "r"(__float_as_uint(b[nt].y)));
                }
            }
        }

        // ---- epilogue: direct STG.64; 4 lanes x 8B = 32B contiguous per row ----
        float2* og = reinterpret_cast<float2*>(out) + (size_t)t * 128 * 64;
#pragma unroll
        for (int mf = 0; mf < 2; mf++) {
            int r0 = wm * 32 + mf * 16 + (lane >> 2);
#pragma unroll
            for (int nt = 0; nt < 4; nt++) {
                int colp = wn * 16 + nt * 4 + (lane & 3);
                og[(size_t)r0 * 64 + colp]       = make_float2(acc[mf][nt][0], acc[mf][nt][1]);
                og[(size_t)(r0 + 8) * 64 + colp] = make_float2(acc[mf][nt][2], acc[mf][nt][3]);
            }
        }
        __syncthreads();   // all warps done with buf[cur] before refill
        cur ^= 1;
    }
}

// ---------------------------------------------------------------------------
extern "C" void kernel_launch(void* const* d_in, const int* in_sizes, int n_in,
                              void* d_out, int out_size) {
    const float* x      = (const float*)d_in[0];
    const float* logits = (const float*)d_in[1];
    const float* u      = (const float*)d_in[2];
    float*       out    = (float*)d_out;

    int dev = 0, sms = 148;
    cudaGetDevice(&dev);
    cudaDeviceGetAttribute(&sms, cudaDevAttrMultiProcessorCount, dev);

    cudaFuncSetAttribute(fused_kernel, cudaFuncAttributeMaxDynamicSharedMemorySize, SMEM_BYTES);

    int rows   = in_sizes[0] / 128;   // 524288
    int ntiles = rows / 128;          // 4096
    fused_kernel<<<sms, 512, SMEM_BYTES>>>(x, logits, u, out, ntiles);
}

// round 4
// speedup vs baseline: 1.0673x; 1.0487x over previous
#include <cuda_runtime.h>
#include <cstdint>

// ============================================================================
// out[524288,128] = x @ P^T, P = Sinkhorn(exp(clip((logits+gumbel(u))/3)))
// Fused persistent kernel, 256 threads = 2 independent 4-warp GEMM pipelines.
// Warp tile m64 x n64 (0.125 smem-B/MAC). tf32 mma.sync (tcgen05 unavailable:
// harness targets compute_103, not 103a).
// ============================================================================

#define EPSF 1e-20f

__device__ __forceinline__ uint32_t smem_u32(const void* p) {
    uint32_t a;
    asm("{ .reg .u64 t; cvta.to.shared.u64 t, %1; cvt.u32.u64 %0, t; }" : "=r"(a) : "l"(p));
    return a;
}
__device__ __forceinline__ void cp16(float* dst, const float* src) {
    uint32_t d = smem_u32(dst);
    asm volatile("cp.async.cg.shared.global [%0], [%1], 16;" :: "r"(d), "l"(src) : "memory");
}
__device__ __forceinline__ void cp_commit() { asm volatile("cp.async.commit_group;" ::: "memory"); }
__device__ __forceinline__ void cp_wait0()  { asm volatile("cp.async.wait_group 0;" ::: "memory"); }
__device__ __forceinline__ void barg(int id) {
    asm volatile("bar.sync %0, 128;" :: "r"(id) : "memory");
}

// smem plan (201,728 B): PF 16384 f | XS0 128*132 f | XS1 128*132 f | Rv,Cv 256 f
static constexpr int XS_STRIDE  = 132;
static constexpr int XS_WORDS   = 128 * XS_STRIDE;
static constexpr int PF_FLOATS  = 16384;
static constexpr int SMEM_BYTES = (PF_FLOATS + 2 * XS_WORDS + 256) * 4;

__global__ void __launch_bounds__(256, 1)
fused_kernel(const float* __restrict__ x,
             const float* __restrict__ logits,
             const float* __restrict__ u,
             float* __restrict__ out, int ntiles) {
    extern __shared__ float sh[];
    float*  PF  = sh;
    float*  XS0 = sh + PF_FLOATS;
    float*  XS1 = XS0 + XS_WORDS;
    float*  Rv  = XS1 + XS_WORDS;   // 128
    float*  Cv  = Rv + 128;         // 128
    float2* PF2 = reinterpret_cast<float2*>(PF);

    const int tid  = threadIdx.x;
    const int lane = tid & 31;
    const int wid  = tid >> 5;
    const int gsel = wid >> 2;          // pipeline group 0/1
    const int gtid = tid & 127;
    const int w    = wid & 3;
    const int wm   = w & 1;             // m offset wm*64
    const int wn   = w >> 1;            // n offset wn*64

    const int step = gridDim.x * 2;
    int t = blockIdx.x * 2 + gsel;
    float* XB = gsel ? XS1 : XS0;

    // ---- group 0: prefetch first tile (hidden under sinkhorn; XS0 is free) ----
    if (gsel == 0 && t < ntiles) {
        const float4* g = reinterpret_cast<const float4*>(x) + (size_t)t * 4096;
#pragma unroll
        for (int i = 0; i < 32; i++) {
            int f4 = i * 128 + gtid;
            int m = f4 >> 5, c4 = f4 & 31;
            cp16(XS0 + m * XS_STRIDE + c4 * 4, reinterpret_cast<const float*>(g + f4));
        }
        cp_commit();
    }

    // ================= sinkhorn prologue (A in XS1) ==========================
    {
        float* A = XS1;
        for (int idx = tid; idx < 16384; idx += 256) {
            float uv = u[idx];
            float g  = -logf(-logf(uv + EPSF) + EPSF);
            float la = (logits[idx] + g) * (1.0f / 3.0f);
            la = fminf(10.0f, fmaxf(-10.0f, la));
            A[idx] = expf(la);
        }
        if (tid < 128) Cv[tid] = 1.0f;
        __syncthreads();

        const int i = tid >> 1;     // row/col 0..127
        const int s = tid & 1;      // half selector

        float4 a4[16];              // row i, cols [s*64, s*64+64)
        float  at[64];              // col i, rows [s*64, s*64+64)
#pragma unroll
        for (int k = 0; k < 16; k++)
            a4[k] = *reinterpret_cast<const float4*>(&A[i * 128 + s * 64 + k * 4]);
#pragma unroll
        for (int j = 0; j < 64; j++)
            at[j] = A[(s * 64 + j) * 128 + i];

        for (int it = 0; it < 20; it++) {
            float sum = 0.0f;
#pragma unroll
            for (int k = 0; k < 16; k++) {
                float4 cv = *reinterpret_cast<const float4*>(&Cv[s * 64 + k * 4]);
                sum += a4[k].x * cv.x + a4[k].y * cv.y + a4[k].z * cv.z + a4[k].w * cv.w;
            }
            sum += __shfl_xor_sync(0xffffffffu, sum, 1);
            if (s == 0) Rv[i] = 1.0f / sum;
            __syncthreads();

            float sum2 = 0.0f;
#pragma unroll
            for (int j = 0; j < 64; j += 4) {
                float4 rv = *reinterpret_cast<const float4*>(&Rv[s * 64 + j]);
                sum2 += at[j] * rv.x + at[j + 1] * rv.y + at[j + 2] * rv.z + at[j + 3] * rv.w;
            }
            sum2 += __shfl_xor_sync(0xffffffffu, sum2, 1);
            if (s == 0) Cv[i] = 1.0f / sum2;
            __syncthreads();
        }

        // P = diag(r) A diag(c) * (1+2^-11), tf32-rounded, scattered into
        // B-fragment order: PF2[(s*16+nt)*32+lane] = {P[n][k0], P[n][k0+4]},
        // n = nt*8 + (lane>>2), k0 = s*8 + (lane&3).
        const float comp = 1.0f + 0.00048828125f;
        for (int idx = tid; idx < 16384; idx += 256) {
            int n = idx >> 7, k = idx & 127;
            float p = Rv[n] * A[n * 128 + k] * Cv[k] * comp;
            float pt;
            asm("cvt.rna.tf32.f32 %0, %1;" : "=f"(pt) : "f"(p));
            int ss = k >> 3, ko = k & 7;
            int fi = ((ss * 16 + (n >> 3)) * 32 + (n & 7) * 4 + (ko & 3)) * 2 + (ko >> 2);
            PF[fi] = pt;
        }
        __syncthreads();   // A (XS1) dead; PF ready
    }

    // ---- group 1: issue its first tile load (XS1 now free) ----
    if (gsel == 1 && t < ntiles) {
        const float4* g = reinterpret_cast<const float4*>(x) + (size_t)t * 4096;
#pragma unroll
        for (int i = 0; i < 32; i++) {
            int f4 = i * 128 + gtid;
            int m = f4 >> 5, c4 = f4 & 31;
            cp16(XS1 + m * XS_STRIDE + c4 * 4, reinterpret_cast<const float*>(g + f4));
        }
        cp_commit();
    }

    // ================= per-group persistent mainloop =========================
    const int bid = gsel + 1;   // named barrier id per group

    for (; t < ntiles; t += step) {
        cp_wait0();
        barg(bid);               // tile t resident in XB for all 4 warps

        float acc[4][8][4];
#pragma unroll
        for (int mf = 0; mf < 4; mf++)
#pragma unroll
            for (int nt = 0; nt < 8; nt++)
#pragma unroll
                for (int q = 0; q < 4; q++) acc[mf][nt][q] = 0.0f;

#pragma unroll
        for (int s = 0; s < 16; s++) {
            float2 b[8];
#pragma unroll
            for (int nt = 0; nt < 8; nt++)
                b[nt] = PF2[(s * 16 + wn * 8 + nt) * 32 + lane];

#pragma unroll
            for (int mf = 0; mf < 4; mf++) {
                int r0 = wm * 64 + mf * 16 + (lane >> 2);
                int cc = s * 8 + (lane & 3);
                uint32_t a0 = __float_as_uint(XB[r0 * XS_STRIDE + cc]);
                uint32_t a1 = __float_as_uint(XB[(r0 + 8) * XS_STRIDE + cc]);
                uint32_t a2 = __float_as_uint(XB[r0 * XS_STRIDE + cc + 4]);
                uint32_t a3 = __float_as_uint(XB[(r0 + 8) * XS_STRIDE + cc + 4]);
#pragma unroll
                for (int nt = 0; nt < 8; nt++) {
                    asm volatile(
                        "mma.sync.aligned.m16n8k8.row.col.f32.tf32.tf32.f32 "
                        "{%0,%1,%2,%3}, {%4,%5,%6,%7}, {%8,%9}, {%0,%1,%2,%3};"
                        : "+f"(acc[mf][nt][0]), "+f"(acc[mf][nt][1]),
                          "+f"(acc[mf][nt][2]), "+f"(acc[mf][nt][3])
                        : "r"(a0), "r"(a1), "r"(a2), "r"(a3),
                          "r"(__float_as_uint(b[nt].x)), "r"(__float_as_uint(b[nt].y)));
                }
            }
        }

        barg(bid);               // all 4 warps done reading XB

        // issue next tile into XB (overlaps with epilogue stores)
        int tn = t + step;
        if (tn < ntiles) {
            const float4* g = reinterpret_cast<const float4*>(x) + (size_t)tn * 4096;
#pragma unroll
            for (int i = 0; i < 32; i++) {
                int f4 = i * 128 + gtid;
                int m = f4 >> 5, c4 = f4 & 31;
                cp16(XB + m * XS_STRIDE + c4 * 4, reinterpret_cast<const float*>(g + f4));
            }
        }
        cp_commit();

        // epilogue: direct STG.64 (each quad covers one 32B sector)
        float2* og = reinterpret_cast<float2*>(out) + (size_t)t * 128 * 64;
#pragma unroll
        for (int mf = 0; mf < 4; mf++) {
            int r0 = wm * 64 + mf * 16 + (lane >> 2);
#pragma unroll
            for (int nt = 0; nt < 8; nt++) {
                int colp = wn * 32 + nt * 4 + (lane & 3);
                og[(size_t)r0 * 64 + colp]       = make_float2(acc[mf][nt][0], acc[mf][nt][1]);
                og[(size_t)(r0 + 8) * 64 + colp] = make_float2(acc[mf][nt][2], acc[mf][nt][3]);
            }
        }
    }
}

// ---------------------------------------------------------------------------
extern "C" void kernel_launch(void* const* d_in, const int* in_sizes, int n_in,
                              void* d_out, int out_size) {
    const float* x      = (const float*)d_in[0];
    const float* logits = (const float*)d_in[1];
    const float* u      = (const float*)d_in[2];
    float*       out    = (float*)d_out;

    int dev = 0, sms = 148;
    cudaGetDevice(&dev);
    cudaDeviceGetAttribute(&sms, cudaDevAttrMultiProcessorCount, dev);

    cudaFuncSetAttribute(fused_kernel, cudaFuncAttributeMaxDynamicSharedMemorySize, SMEM_BYTES);

    int rows   = in_sizes[0] / 128;   // 524288
    int ntiles = rows / 128;          // 4096
    fused_kernel<<<sms, 256, SMEM_BYTES>>>(x, logits, u, out, ntiles);
}